// round 17
// baseline (speedup 1.0000x reference)
#include <cuda_runtime.h>
#include <cuda_fp16.h>
#include <mma.h>
#include <math.h>

using namespace nvcuda;

#define Bz    8
#define Nn    2048
#define INC   256
#define OUTC  128
#define NAUG  144              // 128 g-cols + 8 score cols + 8 zero pad
#define EDG   65536
#define ROWS  (Bz*Nn)          // 16384
#define CAPD  128              // per-dst CSR capacity (Poisson(32): P(>128)~0)
#define BN_EPS 1e-5f

// ---------------- scratch (static device globals; no runtime alloc) --------
__device__ __half d_Waug[INC*NAUG];       // [Wg | Wsd | 0] fp16 [256][144]
__device__ __half d_g16[ROWS*OUTC];       // g, NODE-MAJOR: [n][b][c] fp16 (4 MB)
__device__ float4 d_ssrc[ROWS];           // NODE-MAJOR: [n][b]
__device__ float4 d_sdst[ROWS];           // NODE-MAJOR: [n][b]
__device__ unsigned d_bitmap[(Nn*Nn)/32]; // 512 KB dedup bitmap
__device__ int d_counts[Nn];              // per-dst degree (append cursor)
__device__ int d_colp[Nn*CAPD];           // padded CSR: [dst][CAPD]
__device__ float d_ssum[OUTC];
__device__ float d_ssumsq[OUTC];
__device__ int d_is64;

// ---------------- prep: bitmap/count reset + dtype sniff + weight fold -------
// grid 384 x 256: blocks 0..127 reset; blocks 128..383 fold W,a into Waug.
__global__ void k_prep(const unsigned* __restrict__ ei32,
                       const float* __restrict__ W,
                       const float* __restrict__ a) {
    __shared__ float part[4][8];
    int bid = blockIdx.x, tid = threadIdx.x;
    if (bid < 128) {
        int i = bid*256 + tid;                           // 0..32767
        ((uint4*)d_bitmap)[i] = make_uint4(0u,0u,0u,0u); // 512 KB
        if (i < Nn)  d_counts[i] = 0;
        if (i < OUTC){ d_ssum[i] = 0.f; d_ssumsq[i] = 0.f; }
        if (i == 0) {
            int is64 = 1;
            #pragma unroll 1
            for (int t = 1; t < 128; t += 2)
                if (ei32[t] != 0u) { is64 = 0; break; }
            d_is64 = is64;
        }
    } else {
        int k    = bid - 128;        // 0..255
        int c    = tid & 127;
        int grp  = tid >> 7;         // 0: src (j 0..3), 1: dst (j 4..7)
        int lane = tid & 31;
        int cw   = c >> 5;           // c-warp 0..3
        float w0 = W[k*512 +       c];
        float w1 = W[k*512 + 128 + c];
        float w2 = W[k*512 + 256 + c];
        float w3 = W[k*512 + 384 + c];
        if (grp == 0) d_Waug[k*NAUG + c] = __float2half(0.25f*(w0+w1+w2+w3));
        float av = (grp == 0) ? a[c] : a[128+c];
        float vals[4] = {w0*av, w1*av, w2*av, w3*av};
        #pragma unroll
        for (int jj = 0; jj < 4; jj++) {
            float v = vals[jj];
            #pragma unroll
            for (int off = 16; off; off >>= 1) v += __shfl_xor_sync(0xffffffff, v, off);
            if (lane == 0) part[cw][grp*4 + jj] = v;
        }
        __syncthreads();
        if (tid < 8)
            d_Waug[k*NAUG + 128 + tid] =
                __float2half(part[0][tid] + part[1][tid] + part[2][tid] + part[3][tid]);
        else if (tid < 16)
            d_Waug[k*NAUG + 128 + tid] = __float2half(0.f);
    }
}

__device__ __forceinline__ int edge_at(const void* ei, int idx) {
    if (d_is64) return (int)((const long long*)ei)[idx];
    return ((const int*)ei)[idx];
}

// ---------------- dedup + direct padded-CSR append (2 edges/thread) ----------
__global__ void k_dedup(const void* __restrict__ ei) {
    int e0 = (blockIdx.x*blockDim.x + threadIdx.x) * 2;
    if (e0 >= EDG) return;
    int s0 = edge_at(ei, e0),     s1 = edge_at(ei, e0+1);
    int d0 = edge_at(ei, EDG+e0), d1 = edge_at(ei, EDG+e0+1);
    int ss[2] = {s0, s1};
    int dd[2] = {d0, d1};
    #pragma unroll
    for (int i = 0; i < 2; i++) {
        unsigned key = (unsigned)dd[i]*(unsigned)Nn + (unsigned)ss[i];
        unsigned mask = 1u << (key & 31);
        unsigned old = atomicOr(&d_bitmap[key >> 5], mask);
        if (!(old & mask)) {
            int pos = atomicAdd(&d_counts[dd[i]], 1);
            if (pos < CAPD) d_colp[dd[i]*CAPD + pos] = ss[i];
        }
    }
}

// ---------------- fused GEMM: [g | scores] = x @ Waug, double-buffered -------
__global__ void __launch_bounds__(256) k_gemm_g(const float* __restrict__ x) {
    __shared__ union SM {
        struct {
            __half xa[64][40];
            __half ws[32][152];
        } m[2];
        float stage[64][152];
    } sm;

    int block_row = blockIdx.x * 64;
    int tid  = threadIdx.x;
    int wid  = tid >> 5;
    int wr   = (wid >> 1) * 16;
    int wc   = (wid & 1) * 64;

    wmma::fragment<wmma::accumulator, 16, 16, 16, float> acc[4];
    wmma::fragment<wmma::accumulator, 16, 16, 16, float> accS;
    #pragma unroll
    for (int c = 0; c < 4; c++) wmma::fill_fragment(acc[c], 0.f);
    wmma::fill_fragment(accS, 0.f);

    float4 xv[2];
    uint4  wv[3];
    int wf[3], wk[3], wc8[3];
    #pragma unroll
    for (int i = 0; i < 3; i++) {
        wf[i] = i*256 + tid;
        wk[i] = wf[i] / 18;
        wc8[i] = (wf[i] - wk[i]*18) * 8;
    }
    int xrow[2], xkq[2];
    #pragma unroll
    for (int i = 0; i < 2; i++) {
        int f = i*256 + tid;
        xrow[i] = f >> 3;
        xkq[i]  = f & 7;
    }

    auto load_regs = [&](int kt) {
        #pragma unroll
        for (int i = 0; i < 2; i++)
            xv[i] = *(const float4*)(x + (size_t)(block_row+xrow[i])*INC + kt + xkq[i]*4);
        #pragma unroll
        for (int i = 0; i < 3; i++)
            if (wf[i] < 576)
                wv[i] = *(const uint4*)&d_Waug[(kt+wk[i])*NAUG + wc8[i]];
    };
    auto store_tile = [&](int buf) {
        #pragma unroll
        for (int i = 0; i < 2; i++) {
            __half2 h0 = __floats2half2_rn(xv[i].x, xv[i].y);
            __half2 h1 = __floats2half2_rn(xv[i].z, xv[i].w);
            uint2 u; u.x = *(unsigned*)&h0; u.y = *(unsigned*)&h1;
            *(uint2*)&sm.m[buf].xa[xrow[i]][xkq[i]*4] = u;
        }
        #pragma unroll
        for (int i = 0; i < 3; i++)
            if (wf[i] < 576)
                *(uint4*)&sm.m[buf].ws[wk[i]][wc8[i]] = wv[i];
    };

    load_regs(0);
    store_tile(0);
    __syncthreads();

    int buf = 0;
    #pragma unroll
    for (int t = 0; t < 8; t++) {
        if (t < 7) load_regs((t+1)*32);

        #pragma unroll
        for (int ks = 0; ks < 32; ks += 16) {
            wmma::fragment<wmma::matrix_a, 16, 16, 16, __half, wmma::row_major> af;
            wmma::load_matrix_sync(af, &sm.m[buf].xa[wr][ks], 40);
            #pragma unroll
            for (int c = 0; c < 4; c++) {
                wmma::fragment<wmma::matrix_b, 16, 16, 16, __half, wmma::row_major> bf;
                wmma::load_matrix_sync(bf, &sm.m[buf].ws[ks][wc + c*16], 152);
                wmma::mma_sync(acc[c], af, bf, acc[c]);
            }
            if (wc == 0) {
                wmma::fragment<wmma::matrix_b, 16, 16, 16, __half, wmma::row_major> bf;
                wmma::load_matrix_sync(bf, &sm.m[buf].ws[ks][128], 152);
                wmma::mma_sync(accS, af, bf, accS);
            }
        }
        if (t < 7) {
            store_tile(buf ^ 1);
            __syncthreads();
            buf ^= 1;
        }
    }
    __syncthreads();

    #pragma unroll
    for (int c = 0; c < 4; c++)
        wmma::store_matrix_sync(&sm.stage[wr][wc + c*16], acc[c], 152, wmma::mem_row_major);
    if (wc == 0)
        wmma::store_matrix_sync(&sm.stage[wr][128], accS, 152, wmma::mem_row_major);
    __syncthreads();

    int tx = tid & 15;
    int ty = tid >> 4;
    #pragma unroll
    for (int r = ty; r < 64; r += 16) {
        int row = block_row + r;
        int bb = row >> 11;
        int nn = row & (Nn-1);
        const float* st = &sm.stage[r][tx*8];
        __half2 h0 = __floats2half2_rn(st[0], st[1]);
        __half2 h1 = __floats2half2_rn(st[2], st[3]);
        __half2 h2 = __floats2half2_rn(st[4], st[5]);
        __half2 h3 = __floats2half2_rn(st[6], st[7]);
        uint4 u;
        u.x = *(unsigned*)&h0; u.y = *(unsigned*)&h1;
        u.z = *(unsigned*)&h2; u.w = *(unsigned*)&h3;
        *(uint4*)&d_g16[(size_t)(nn*8 + bb)*OUTC + tx*8] = u;   // node-major
    }

    if (tid < 128) {
        int srow = tid >> 1;
        int sq   = (tid & 1) * 4;
        const float* st = &sm.stage[srow][128 + sq];
        float4 sv = make_float4(st[0], st[1], st[2], st[3]);
        int grow = block_row + srow;
        int gb_ = grow >> 11;
        int gn  = grow & (Nn-1);
        if (sq == 0) d_ssrc[gn*8 + gb_] = sv;
        else         d_sdst[gn*8 + gb_] = sv;
    }
}

__device__ __forceinline__ float edge_val(float4 ss, float4 sd) {
    float v0 = ss.x + sd.x, v1 = ss.y + sd.y, v2 = ss.z + sd.z, v3 = ss.w + sd.w;
    v0 = v0 > 0.f ? v0 : 0.2f*v0;
    v1 = v1 > 0.f ? v1 : 0.2f*v1;
    v2 = v2 > 0.f ? v2 : 0.2f*v2;
    v3 = v3 > 0.f ? v3 : 0.2f*v3;
    return 0.25f*(v0+v1+v2+v3);
}

// ---------------- agg: 2 dst per block, warp/batch, HFMA2 gather -------------
// Gather accumulates in fp16 (HFMA2, 4 ops per 16B) and flushes to fp32 every
// 16 edges (chain <= 8 per parity) — error contribution ~2e-4, under budget.
__global__ void __launch_bounds__(256) k_agg(float* __restrict__ out) {
    int tid  = threadIdx.x;
    int b    = tid >> 5;            // warp = batch
    int lane = tid & 31;
    int lp   = lane >> 4;           // edge parity (0/1)
    int c16  = lane & 15;           // 16-byte channel group (8 halves)

    __shared__ int   scol[CAPD];
    __shared__ float sp[8][CAPD];
    __shared__ float sb[8][128];
    __shared__ float sb2[8][128];

    float bnsum[8], bnsq[8];
    #pragma unroll
    for (int q = 0; q < 8; q++) { bnsum[q] = 0.f; bnsq[q] = 0.f; }

    const uint4* gb16 = (const uint4*)d_g16;   // row (n*8+b) = 16 uint4

    #pragma unroll 1
    for (int it = 0; it < 2; it++) {
        int d   = blockIdx.x*2 + it;
        int cnt = min(d_counts[d], CAPD);
        float4* o4 = (float4*)(out + ((size_t)b*Nn + d)*OUTC);

        __syncthreads();                         // protect scol/sp reuse
        if (tid < cnt) scol[tid] = __ldg(&d_colp[d*CAPD + tid]);
        __syncthreads();

        if (cnt == 0) { o4[lane] = make_float4(0.f,0.f,0.f,0.f); continue; }

        float4 sd = d_sdst[d*8 + b];
        float lsum = 0.f;
        for (int jj = lane; jj < cnt; jj += 32) {
            int s = scol[jj];
            float p = __expf(edge_val(d_ssrc[s*8 + b], sd));
            sp[b][jj] = p;
            lsum += p;
        }
        __syncwarp();

        // fp32 master accumulators (packed as float2 lanes)
        float2 f01 = make_float2(0.f,0.f), f23 = make_float2(0.f,0.f);
        float2 f45 = make_float2(0.f,0.f), f67 = make_float2(0.f,0.f);

        for (int cbase = 0; cbase < cnt; cbase += 16) {
            int hi = min(cbase + 16, cnt);
            __half2 h01 = __float2half2_rn(0.f), h23 = h01, h45 = h01, h67 = h01;
            #pragma unroll 4
            for (int jj = cbase + lp; jj < hi; jj += 2) {
                float p = sp[b][jj];
                uint4 u = __ldg(gb16 + (size_t)(scol[jj]*8 + b)*16 + c16);
                __half2 ph = __float2half2_rn(p);
                h01 = __hfma2(ph, *(__half2*)&u.x, h01);
                h23 = __hfma2(ph, *(__half2*)&u.y, h23);
                h45 = __hfma2(ph, *(__half2*)&u.z, h45);
                h67 = __hfma2(ph, *(__half2*)&u.w, h67);
            }
            float2 t;
            t = __half22float2(h01); f01.x += t.x; f01.y += t.y;
            t = __half22float2(h23); f23.x += t.x; f23.y += t.y;
            t = __half22float2(h45); f45.x += t.x; f45.y += t.y;
            t = __half22float2(h67); f67.x += t.x; f67.y += t.y;
        }

        #pragma unroll
        for (int off = 16; off; off >>= 1)
            lsum += __shfl_xor_sync(0xffffffff, lsum, off);
        float inv = 1.f / lsum;

        float v[8] = {f01.x,f01.y,f23.x,f23.y,f45.x,f45.y,f67.x,f67.y};
        #pragma unroll
        for (int q = 0; q < 8; q++) {
            v[q] += __shfl_xor_sync(0xffffffff, v[q], 16);   // combine edge parities
            v[q] *= inv;
        }
        if (lp == 0) {
            o4[c16*2]   = make_float4(v[0], v[1], v[2], v[3]);
            o4[c16*2+1] = make_float4(v[4], v[5], v[6], v[7]);
            #pragma unroll
            for (int q = 0; q < 8; q++) { bnsum[q] += v[q]; bnsq[q] += v[q]*v[q]; }
        }
    }

    // BN tail (once): lane<16 holds channels c16*8..+7
    if (lp == 0) {
        #pragma unroll
        for (int q = 0; q < 8; q++) {
            sb [b][c16*8 + q] = bnsum[q];
            sb2[b][c16*8 + q] = bnsq[q];
        }
    }
    __syncthreads();
    if (tid < 128) {
        float s = 0.f, s2 = 0.f;
        #pragma unroll
        for (int w = 0; w < 8; w++) { s += sb[w][tid]; s2 += sb2[w][tid]; }
        atomicAdd(&d_ssum[tid], s);
        atomicAdd(&d_ssumsq[tid], s2);
    }
}

// ---------------- BN apply + ELU (in place, float4, fast exp) ----------------
__global__ void k_final(float* __restrict__ out,
                        const float* __restrict__ gamma,
                        const float* __restrict__ beta) {
    int i = blockIdx.x*blockDim.x + threadIdx.x;     // float4 index
    if (i >= ROWS*OUTC/4) return;
    int c0 = (i*4) & (OUTC-1);
    const float inv = 1.f/(float)ROWS;
    float4 v = ((const float4*)out)[i];
    float r[4] = {v.x, v.y, v.z, v.w};
    #pragma unroll
    for (int j = 0; j < 4; j++) {
        int c = c0 + j;
        float mean = d_ssum[c]  * inv;
        float var  = d_ssumsq[c]* inv - mean*mean;
        float y = (r[j] - mean) * rsqrtf(var + BN_EPS) * __ldg(&gamma[c]) + __ldg(&beta[c]);
        r[j] = y > 0.f ? y : (__expf(y) - 1.f);
    }
    ((float4*)out)[i] = make_float4(r[0], r[1], r[2], r[3]);
}

// ---------------- launch: fork-join graph ------------------------------------
extern "C" void kernel_launch(void* const* d_in, const int* in_sizes, int n_in,
                              void* d_out, int out_size) {
    const float* x     = (const float*)d_in[0];
    const void*  ei    = d_in[1];
    const float* W     = (const float*)d_in[2];
    const float* a     = (const float*)d_in[3];
    const float* gamma = (const float*)d_in[4];
    const float* beta  = (const float*)d_in[5];
    float* out = (float*)d_out;

    static cudaStream_t s1 = nullptr;
    static cudaEvent_t  e0 = nullptr, e1 = nullptr;
    if (s1 == nullptr) {
        cudaStreamCreateWithFlags(&s1, cudaStreamNonBlocking);
        cudaEventCreateWithFlags(&e0, cudaEventDisableTiming);
        cudaEventCreateWithFlags(&e1, cudaEventDisableTiming);
    }

    // main: prep (reset + weights)
    k_prep<<<384, 256>>>((const unsigned*)ei, W, a);
    cudaEventRecord(e0, 0);

    // side: dedup (needs prep's bitmap clear)
    cudaStreamWaitEvent(s1, e0, 0);
    k_dedup<<<EDG/512, 256, 0, s1>>>(ei);
    cudaEventRecord(e1, s1);

    // main: fused fp16 GEMM (+tensorized scores), concurrent with dedup
    k_gemm_g<<<ROWS/64, 256>>>(x);

    // join: aggregation (+BN stats) + BN/ELU
    cudaStreamWaitEvent(0, e1, 0);
    k_agg  <<<Nn/2, 256>>>(out);
    k_final<<<(ROWS*OUTC/4 + 255)/256, 256>>>(out, gamma, beta);
}